// round 7
// baseline (speedup 1.0000x reference)
#include <cuda_runtime.h>
#include <cuda_bf16.h>

// Problem constants: IN=4, H=30, OUT=1, N_UNIT=100, B=262144
#define NU    100
#define HH    30
#define NT    256          // threads per block
#define RPB   NT           // 1 row per thread -> 256 rows per block
#define KP    (HH / 2)     // 15 packed k-pairs

typedef unsigned long long u64;

// ---- packed f32x2 helpers (sm_103a) ----
__device__ __forceinline__ u64 ffma2(u64 a, u64 b, u64 c) {
    u64 d;
    asm("fma.rn.f32x2 %0, %1, %2, %3;" : "=l"(d) : "l"(a), "l"(b), "l"(c));
    return d;
}
__device__ __forceinline__ u64 pack2(float x, float y) {
    u64 d;
    asm("mov.b64 %0, {%1, %2};" : "=l"(d) : "f"(x), "f"(y));
    return d;
}
__device__ __forceinline__ float2 unpack2(u64 a) {
    float2 f;
    asm("mov.b64 {%0, %1}, %2;" : "=f"(f.x), "=f"(f.y) : "l"(a));
    return f;
}
__device__ __forceinline__ u64 relu2(u64 a) {
    float2 f = unpack2(a);
    return pack2(fmaxf(f.x, 0.0f), fmaxf(f.y, 0.0f));
}

// ---------------------------------------------------------------------------
// Fused kernel: per-block merit-order setup, 1 row/thread MLP with k-packed
// f32x2 accumulators (30 acc regs), register-cached dispatch stores.
// ---------------------------------------------------------------------------
__global__ __launch_bounds__(NT, 4)
void mlp_dispatch_kernel(const float4* __restrict__ x,     // [B,4] as float4
                         const float*  __restrict__ Cost,  // [100]
                         const float*  __restrict__ Pmax,  // [100]
                         const float*  __restrict__ Pd,    // [100]
                         const float*  __restrict__ wcap,  // [1]
                         const float*  __restrict__ W1,    // [4,30]
                         const float*  __restrict__ b1,    // [30]
                         const float*  __restrict__ W2,    // [30,30]
                         const float*  __restrict__ b2,    // [30]
                         const float*  __restrict__ W3,    // [30,1]
                         const float*  __restrict__ b3,    // [1]
                         float*        __restrict__ out)   // [B,100]
{
    __shared__ alignas(16) float sW1[4 * HH];    // scalar layer-1 weights
    __shared__ alignas(16) float sb1[HH];
    __shared__ alignas(16) float sW2[HH * 32];   // W2 rows padded to 32 floats
    __shared__ alignas(16) float sb2[HH];
    __shared__ alignas(16) float sW3[HH];
    __shared__ alignas(16) float sCost[NU];
    __shared__ alignas(16) float sCum[NU];
    __shared__ alignas(16) float sPmax[NU];
    __shared__ alignas(16) float sTd[RPB];
    __shared__ float sB3, sWc, sSum;

    const int tid = threadIdx.x;

    // ---- Stage params ----
    for (int i = tid; i < HH * 32; i += NT) {
        int r = i >> 5, c = i & 31;
        sW2[i] = (c < HH) ? W2[r * HH + c] : 0.0f;
    }
    if (tid < 4 * HH) sW1[tid] = W1[tid];
    if (tid < HH) { sb1[tid] = b1[tid]; sb2[tid] = b2[tid]; sW3[tid] = W3[tid]; }
    if (tid < NU) { sCost[tid] = Cost[tid]; sPmax[tid] = Pmax[tid]; }
    if (tid == 0) { sB3 = b3[0]; sWc = wcap[0]; }
    if (tid >= NT - 32) {          // last warp: parallel sum(Pd)
        int l = tid - (NT - 32);
        float s = 0.0f;
        for (int j = l; j < NU; j += 32) s += Pd[j];
        #pragma unroll
        for (int o = 16; o > 0; o >>= 1)
            s += __shfl_xor_sync(0xFFFFFFFFu, s, o);
        if (l == 0) sSum = s;
    }
    __syncthreads();

    // ---- Merit order (stable argsort closed form), per original unit ----
    if (tid < NU) {
        const float cj = sCost[tid];
        float cum = 0.0f;
        #pragma unroll 4
        for (int k = 0; k < NU; k++) {
            float ck = sCost[k];
            bool cheaper = (ck < cj) || (ck == cj && k < tid);
            if (cheaper) cum += sPmax[k];
        }
        sCum[tid] = cum;
    }

    // ---- this thread's single row ----
    const int row = blockIdx.x * NT + tid;
    const float4 xv = x[row];

    __syncthreads();

    // ---- layer-2 accumulators, k-packed: acc[kp] = (h2[2kp], h2[2kp+1]) ----
    u64 acc[KP];
    #pragma unroll
    for (int kp = 0; kp < KP; kp++)
        acc[kp] = *reinterpret_cast<const u64*>(&sb2[2 * kp]);

    // ---- fused layer1 (scalar) + layer2 (k-packed), one hidden unit at a time
    #pragma unroll
    for (int i = 0; i < HH; i++) {
        float a = sb1[i];
        a = fmaf(xv.x, sW1[0 * HH + i], a);
        a = fmaf(xv.y, sW1[1 * HH + i], a);
        a = fmaf(xv.z, sW1[2 * HH + i], a);
        a = fmaf(xv.w, sW1[3 * HH + i], a);
        const float h = fmaxf(a, 0.0f);
        const u64 hd = pack2(h, h);

        const float* wrow = &sW2[i * 32];
        #pragma unroll
        for (int q = 0; q < 7; q++) {        // k-pairs 0..13 (LDS.128 = 2 pairs)
            ulonglong2 wv = *reinterpret_cast<const ulonglong2*>(wrow + 4 * q);
            acc[2 * q]     = ffma2(hd, wv.x, acc[2 * q]);
            acc[2 * q + 1] = ffma2(hd, wv.y, acc[2 * q + 1]);
        }
        {                                     // k-pair 14
            u64 wv = *reinterpret_cast<const u64*>(wrow + 28);
            acc[14] = ffma2(hd, wv, acc[14]);
        }
    }

    // ---- output layer: y = b3 + sum_k relu(h2[k]) * W3[k] ----
    u64 yp = pack2(sB3, 0.0f);
    #pragma unroll
    for (int kp = 0; kp < KP; kp++) {
        u64 w3p = *reinterpret_cast<const u64*>(&sW3[2 * kp]);
        yp = ffma2(relu2(acc[kp]), w3p, yp);
    }
    const float2 yv = unpack2(yp);

    sTd[tid] = sSum - sWc * (yv.x + yv.y);
    __syncthreads();

    // ---- dispatch + store: register-cached cu/pm per fixed vec4-column ----
    // 200 active threads: g = t%25 (column group), r0 = t/25 (0..7).
    // Per iteration block writes 8 complete rows; each warp's stores are a
    // contiguous 512B span (quads 8it*25 + 32w .. +31).
    if (tid < 200) {
        const int g  = tid % 25;
        const int r0 = tid / 25;
        const float4 cu4 = *reinterpret_cast<const float4*>(sCum  + 4 * g);
        const float4 pm4 = *reinterpret_cast<const float4*>(sPmax + 4 * g);
        float4* outv = reinterpret_cast<float4*>(out + (size_t)blockIdx.x * RPB * NU);
        #pragma unroll 4
        for (int it = 0; it < RPB / 8; it++) {   // 32 iterations
            const int r = r0 + 8 * it;
            const float t = sTd[r];
            float4 p;
            p.x = fminf(fmaxf(t - cu4.x, 0.0f), pm4.x);
            p.y = fminf(fmaxf(t - cu4.y, 0.0f), pm4.y);
            p.z = fminf(fmaxf(t - cu4.z, 0.0f), pm4.z);
            p.w = fminf(fmaxf(t - cu4.w, 0.0f), pm4.w);
            outv[r * 25 + g] = p;
        }
    }
}

// ---------------------------------------------------------------------------
// Launch. Input order: x, Cost, Pmax, Pd, w_capacity, W1, b1, W2, b2, W3, b3
// ---------------------------------------------------------------------------
extern "C" void kernel_launch(void* const* d_in, const int* in_sizes, int n_in,
                              void* d_out, int out_size) {
    const float* x     = (const float*)d_in[0];
    const float* Cost  = (const float*)d_in[1];
    const float* Pmax  = (const float*)d_in[2];
    const float* Pd    = (const float*)d_in[3];
    const float* wcap  = (const float*)d_in[4];
    const float* W1    = (const float*)d_in[5];
    const float* b1    = (const float*)d_in[6];
    const float* W2    = (const float*)d_in[7];
    const float* b2    = (const float*)d_in[8];
    const float* W3    = (const float*)d_in[9];
    const float* b3    = (const float*)d_in[10];
    float* out = (float*)d_out;

    const int B = in_sizes[0] / 4;      // x is [B, 4]
    const int blocks = B / RPB;         // 262144 / 256 = 1024

    mlp_dispatch_kernel<<<blocks, NT>>>(
        (const float4*)x, Cost, Pmax, Pd, wcap, W1, b1, W2, b2, W3, b3, out);
}

// round 9
// speedup vs baseline: 1.1359x; 1.1359x over previous
#include <cuda_runtime.h>
#include <cuda_bf16.h>

// Problem constants: IN=4, H=30, OUT=1, N_UNIT=100, B=262144
#define NU    100
#define HH    30
#define NT    256          // threads per block
#define RPT   2            // rows per thread
#define RPB   (NT * RPT)   // 512 rows per block

typedef unsigned long long u64;

// ---- packed f32x2 helpers (sm_103a) ----
__device__ __forceinline__ u64 ffma2(u64 a, u64 b, u64 c) {
    u64 d;
    asm("fma.rn.f32x2 %0, %1, %2, %3;" : "=l"(d) : "l"(a), "l"(b), "l"(c));
    return d;
}
__device__ __forceinline__ u64 pack2(float x, float y) {
    u64 d;
    asm("mov.b64 %0, {%1, %2};" : "=l"(d) : "f"(x), "f"(y));
    return d;
}
__device__ __forceinline__ float2 unpack2(u64 a) {
    float2 f;
    asm("mov.b64 {%0, %1}, %2;" : "=f"(f.x), "=f"(f.y) : "l"(a));
    return f;
}
__device__ __forceinline__ u64 relu2(u64 a) {
    float2 f = unpack2(a);
    return pack2(fmaxf(f.x, 0.0f), fmaxf(f.y, 0.0f));
}

// ---------------------------------------------------------------------------
// Fused kernel: per-block merit-order setup; 2 rows/thread MLP with the
// k-dimension split into two passes (8 k-pairs live at a time -> 32 acc regs);
// register-cached coalesced dispatch stores.
// ---------------------------------------------------------------------------
__global__ __launch_bounds__(NT, 3)
void mlp_dispatch_kernel(const float4* __restrict__ x,     // [B,4] as float4
                         const float*  __restrict__ Cost,  // [100]
                         const float*  __restrict__ Pmax,  // [100]
                         const float*  __restrict__ Pd,    // [100]
                         const float*  __restrict__ wcap,  // [1]
                         const float*  __restrict__ W1,    // [4,30]
                         const float*  __restrict__ b1,    // [30]
                         const float*  __restrict__ W2,    // [30,30]
                         const float*  __restrict__ b2,    // [30]
                         const float*  __restrict__ W3,    // [30,1]
                         const float*  __restrict__ b3,    // [1]
                         float*        __restrict__ out)   // [B,100]
{
    __shared__ alignas(16) float4 sW1t[HH];      // transposed: sW1t[i] = W1[0..3][i]
    __shared__ alignas(16) float  sb1[HH];
    __shared__ alignas(16) float  sW2[HH * 32];  // rows padded to 32 floats (zeros)
    __shared__ alignas(16) float  sb2[32];       // padded with zeros
    __shared__ alignas(16) float  sW3[32];       // padded with zeros
    __shared__ alignas(16) float  sCost[NU];
    __shared__ alignas(16) float  sCum[NU];
    __shared__ alignas(16) float  sPmax[NU];
    __shared__ alignas(16) float  sTd[RPB];
    __shared__ float sB3, sWc, sSum;

    const int tid = threadIdx.x;

    // ---- Stage params ----
    for (int i = tid; i < HH * 32; i += NT) {
        int r = i >> 5, c = i & 31;
        sW2[i] = (c < HH) ? W2[r * HH + c] : 0.0f;
    }
    if (tid < 32) {
        sb2[tid] = (tid < HH) ? b2[tid] : 0.0f;
        sW3[tid] = (tid < HH) ? W3[tid] : 0.0f;
    }
    if (tid >= 32 && tid < 32 + HH) {
        int i = tid - 32;
        sW1t[i] = make_float4(W1[0 * HH + i], W1[1 * HH + i],
                              W1[2 * HH + i], W1[3 * HH + i]);
        sb1[i] = b1[i];
    }
    if (tid < NU) { sCost[tid] = Cost[tid]; sPmax[tid] = Pmax[tid]; }
    if (tid == 0) { sB3 = b3[0]; sWc = wcap[0]; }
    if (tid >= NT - 32) {          // last warp: parallel sum(Pd)
        int l = tid - (NT - 32);
        float s = 0.0f;
        for (int j = l; j < NU; j += 32) s += Pd[j];
        #pragma unroll
        for (int o = 16; o > 0; o >>= 1)
            s += __shfl_xor_sync(0xFFFFFFFFu, s, o);
        if (l == 0) sSum = s;
    }
    __syncthreads();

    // ---- Merit order (stable argsort closed form), per original unit ----
    if (tid < NU) {
        const float cj = sCost[tid];
        float cum = 0.0f;
        #pragma unroll 4
        for (int k = 0; k < NU; k++) {
            float ck = sCost[k];
            bool cheaper = (ck < cj) || (ck == cj && k < tid);
            if (cheaper) cum += sPmax[k];
        }
        sCum[tid] = cum;
    }

    // ---- this thread's 2 rows ----
    const long base = (long)blockIdx.x * RPB + 2 * tid;
    const float4 x0 = x[base];
    const float4 x1 = x[base + 1];

    __syncthreads();

    // ---- MLP: two k-half passes; 8 packed k-pairs per pass per row ----
    u64 yp0 = pack2(sB3, 0.0f);
    u64 yp1 = pack2(0.0f, 0.0f);
    #pragma unroll
    for (int p = 0; p < 2; p++) {
        u64 acc0[8], acc1[8];
        #pragma unroll
        for (int q = 0; q < 8; q++) {
            u64 bp = *reinterpret_cast<const u64*>(&sb2[16 * p + 2 * q]);
            acc0[q] = bp;
            acc1[q] = bp;
        }
        #pragma unroll
        for (int i = 0; i < HH; i++) {
            // layer-1 unit i for both rows (recomputed per pass; cheap)
            const float4 w1 = sW1t[i];
            const float  bb = sb1[i];
            float a0 = bb, a1 = bb;
            a0 = fmaf(x0.x, w1.x, a0);  a1 = fmaf(x1.x, w1.x, a1);
            a0 = fmaf(x0.y, w1.y, a0);  a1 = fmaf(x1.y, w1.y, a1);
            a0 = fmaf(x0.z, w1.z, a0);  a1 = fmaf(x1.z, w1.z, a1);
            a0 = fmaf(x0.w, w1.w, a0);  a1 = fmaf(x1.w, w1.w, a1);
            const float h0 = fmaxf(a0, 0.0f);
            const float h1 = fmaxf(a1, 0.0f);
            const u64 h0d = pack2(h0, h0);
            const u64 h1d = pack2(h1, h1);

            // this pass's 16 floats of W2 row i (4x LDS.128, shared by 2 rows)
            const float* wrow = &sW2[i * 32 + 16 * p];
            #pragma unroll
            for (int ql = 0; ql < 4; ql++) {
                ulonglong2 wv = *reinterpret_cast<const ulonglong2*>(wrow + 4 * ql);
                acc0[2 * ql]     = ffma2(h0d, wv.x, acc0[2 * ql]);
                acc1[2 * ql]     = ffma2(h1d, wv.x, acc1[2 * ql]);
                acc0[2 * ql + 1] = ffma2(h0d, wv.y, acc0[2 * ql + 1]);
                acc1[2 * ql + 1] = ffma2(h1d, wv.y, acc1[2 * ql + 1]);
            }
        }
        // fold this k-half into the output dot (padded W3 zeros are harmless)
        #pragma unroll
        for (int q = 0; q < 8; q++) {
            u64 w3p = *reinterpret_cast<const u64*>(&sW3[16 * p + 2 * q]);
            yp0 = ffma2(relu2(acc0[q]), w3p, yp0);
            yp1 = ffma2(relu2(acc1[q]), w3p, yp1);
        }
    }
    const float2 y0 = unpack2(yp0);
    const float2 y1 = unpack2(yp1);

    sTd[2 * tid]     = sSum - sWc * (y0.x + y0.y);
    sTd[2 * tid + 1] = sSum - sWc * (y1.x + y1.y);
    __syncthreads();

    // ---- dispatch + store: register-cached cu/pm per fixed vec4-column ----
    // 200 active threads: g = t%25 (column group), r0 = t/25 (0..7).
    // Per warp each iteration's stores form a contiguous 512B span.
    if (tid < 200) {
        const int g  = tid % 25;
        const int r0 = tid / 25;
        const float4 cu4 = *reinterpret_cast<const float4*>(sCum  + 4 * g);
        const float4 pm4 = *reinterpret_cast<const float4*>(sPmax + 4 * g);
        float4* outv = reinterpret_cast<float4*>(out + (size_t)blockIdx.x * RPB * NU);
        #pragma unroll 4
        for (int it = 0; it < RPB / 8; it++) {   // 64 iterations
            const int r = r0 + 8 * it;
            const float t = sTd[r];
            float4 pq;
            pq.x = fminf(fmaxf(t - cu4.x, 0.0f), pm4.x);
            pq.y = fminf(fmaxf(t - cu4.y, 0.0f), pm4.y);
            pq.z = fminf(fmaxf(t - cu4.z, 0.0f), pm4.z);
            pq.w = fminf(fmaxf(t - cu4.w, 0.0f), pm4.w);
            outv[r * 25 + g] = pq;
        }
    }
}

// ---------------------------------------------------------------------------
// Launch. Input order: x, Cost, Pmax, Pd, w_capacity, W1, b1, W2, b2, W3, b3
// ---------------------------------------------------------------------------
extern "C" void kernel_launch(void* const* d_in, const int* in_sizes, int n_in,
                              void* d_out, int out_size) {
    const float* x     = (const float*)d_in[0];
    const float* Cost  = (const float*)d_in[1];
    const float* Pmax  = (const float*)d_in[2];
    const float* Pd    = (const float*)d_in[3];
    const float* wcap  = (const float*)d_in[4];
    const float* W1    = (const float*)d_in[5];
    const float* b1    = (const float*)d_in[6];
    const float* W2    = (const float*)d_in[7];
    const float* b2    = (const float*)d_in[8];
    const float* W3    = (const float*)d_in[9];
    const float* b3    = (const float*)d_in[10];
    float* out = (float*)d_out;

    const int B = in_sizes[0] / 4;      // x is [B, 4]
    const int blocks = B / RPB;         // 262144 / 512 = 512

    mlp_dispatch_kernel<<<blocks, NT>>>(
        (const float4*)x, Cost, Pmax, Pd, wcap, W1, b1, W2, b2, W3, b3, out);
}